// round 2
// baseline (speedup 1.0000x reference)
#include <cuda_runtime.h>
#include <cuda_bf16.h>
#include <cstdint>

#define D 64
#define D4 16           // D / 4
#define MLP_NT 256      // threads per block in MLP kernel

// ---------------------------------------------------------------------------
// Kernel 1: initialize accumulator (d_out) with x.  h = (1+eps)*x + agg, eps=0,
// so starting the accumulator at x folds the "+x" into the scatter result.
// ---------------------------------------------------------------------------
__global__ void init_kernel(const float4* __restrict__ x4, float4* __restrict__ out4,
                            int n4) {
    int i = blockIdx.x * blockDim.x + threadIdx.x;
    if (i < n4) out4[i] = x4[i];
}

// ---------------------------------------------------------------------------
// Kernel 2: edge-parallel scatter-add.  16 threads per edge; each thread owns
// one float4 chunk of the 64-float feature row.  Vector RED (no return) keeps
// the L2 atomic ALU as the only serialization point.  Grid-stride to bound
// the grid size.
// ---------------------------------------------------------------------------
__global__ void scatter_kernel(const float4* __restrict__ x4,
                               const int* __restrict__ ei,  // [2, E] row-major
                               float4* __restrict__ out4,
                               int E) {
    long long total = (long long)E * D4;
    long long stride = (long long)gridDim.x * blockDim.x;
    for (long long idx = (long long)blockIdx.x * blockDim.x + threadIdx.x;
         idx < total; idx += stride) {
        int e = (int)(idx >> 4);
        int c = (int)(idx & 15);
        int s = ei[e];          // src
        int d = ei[E + e];      // dst
        float4 v = x4[(long long)s * D4 + c];
        float4* p = out4 + (long long)d * D4 + c;
        asm volatile("red.global.add.v4.f32 [%0], {%1, %2, %3, %4};"
                     :: "l"(p), "f"(v.x), "f"(v.y), "f"(v.z), "f"(v.w)
                     : "memory");
    }
}

// ---------------------------------------------------------------------------
// Kernel 3: per-node MLP + ReLU + residual, in-place on d_out.
//   h  = d_out[node]                (= x + agg)
//   t  = relu(h @ W1 + b1)
//   o  = t @ W2 + b2
//   out[node] = x[node] + relu(o)
// W1, W2, b1, b2 in shared (broadcast reads).  Each thread's h row staged in
// shared column-major (hs[k*NT + tid]) -> conflict-free lane-stride-1 access.
// ---------------------------------------------------------------------------
__global__ void mlp_kernel(const float* __restrict__ x,
                           const float* __restrict__ W1,
                           const float* __restrict__ b1,
                           const float* __restrict__ W2,
                           const float* __restrict__ b2,
                           float* __restrict__ out,
                           int N) {
    extern __shared__ float sm[];
    float* W1s = sm;                 // D*D
    float* W2s = W1s + D * D;        // D*D
    float* b1s = W2s + D * D;        // D
    float* b2s = b1s + D;            // D
    float* hs  = b2s + D;            // MLP_NT * D, layout [k][tid]

    int tid = threadIdx.x;
    for (int i = tid; i < D * D; i += MLP_NT) {
        W1s[i] = W1[i];
        W2s[i] = W2[i];
    }
    if (tid < D) { b1s[tid] = b1[tid]; b2s[tid] = b2[tid]; }
    __syncthreads();

    int node = blockIdx.x * MLP_NT + tid;
    if (node >= N) return;

    // stage h row into shared column
    {
        const float4* hrow = (const float4*)(out + (long long)node * D);
        #pragma unroll
        for (int c = 0; c < D4; c++) {
            float4 v = hrow[c];
            hs[(4 * c + 0) * MLP_NT + tid] = v.x;
            hs[(4 * c + 1) * MLP_NT + tid] = v.y;
            hs[(4 * c + 2) * MLP_NT + tid] = v.z;
            hs[(4 * c + 3) * MLP_NT + tid] = v.w;
        }
    }

    // ---- layer 1: t = relu(h @ W1 + b1), buffered in registers ----
    float t[D];
    #pragma unroll
    for (int jt = 0; jt < 4; jt++) {
        float4 acc[4];
        #pragma unroll
        for (int q = 0; q < 4; q++)
            acc[q] = ((const float4*)b1s)[jt * 4 + q];
        for (int k = 0; k < D; k++) {
            float hk = hs[k * MLP_NT + tid];
            const float4* wr = (const float4*)(W1s + k * D + jt * 16);
            #pragma unroll
            for (int q = 0; q < 4; q++) {
                float4 w = wr[q];
                acc[q].x += hk * w.x;
                acc[q].y += hk * w.y;
                acc[q].z += hk * w.z;
                acc[q].w += hk * w.w;
            }
        }
        #pragma unroll
        for (int q = 0; q < 4; q++) {
            t[jt * 16 + q * 4 + 0] = fmaxf(acc[q].x, 0.0f);
            t[jt * 16 + q * 4 + 1] = fmaxf(acc[q].y, 0.0f);
            t[jt * 16 + q * 4 + 2] = fmaxf(acc[q].z, 0.0f);
            t[jt * 16 + q * 4 + 3] = fmaxf(acc[q].w, 0.0f);
        }
    }

    // overwrite shared column with t (all reads of h are done)
    #pragma unroll
    for (int k = 0; k < D; k++) hs[k * MLP_NT + tid] = t[k];

    // ---- layer 2: o = t @ W2 + b2 ; out = x + relu(o) ----
    const float4* xrow = (const float4*)(x + (long long)node * D);
    float4* orow = (float4*)(out + (long long)node * D);
    #pragma unroll
    for (int jt = 0; jt < 4; jt++) {
        float4 acc[4];
        #pragma unroll
        for (int q = 0; q < 4; q++)
            acc[q] = ((const float4*)b2s)[jt * 4 + q];
        for (int k = 0; k < D; k++) {
            float tk = hs[k * MLP_NT + tid];
            const float4* wr = (const float4*)(W2s + k * D + jt * 16);
            #pragma unroll
            for (int q = 0; q < 4; q++) {
                float4 w = wr[q];
                acc[q].x += tk * w.x;
                acc[q].y += tk * w.y;
                acc[q].z += tk * w.z;
                acc[q].w += tk * w.w;
            }
        }
        #pragma unroll
        for (int q = 0; q < 4; q++) {
            float4 xv = xrow[jt * 4 + q];
            float4 o;
            o.x = xv.x + fmaxf(acc[q].x, 0.0f);
            o.y = xv.y + fmaxf(acc[q].y, 0.0f);
            o.z = xv.z + fmaxf(acc[q].z, 0.0f);
            o.w = xv.w + fmaxf(acc[q].w, 0.0f);
            orow[jt * 4 + q] = o;
        }
    }
}

// ---------------------------------------------------------------------------
// Launch
// inputs: 0=x [N,64] f32, 1=edge_index [2,E] i32, 2=W1 [64,64] f32,
//         3=b1 [64] f32, 4=W2 [64,64] f32, 5=b2 [64] f32
// output: [N,64] f32
// ---------------------------------------------------------------------------
extern "C" void kernel_launch(void* const* d_in, const int* in_sizes, int n_in,
                              void* d_out, int out_size) {
    const float* x  = (const float*)d_in[0];
    const int*   ei = (const int*)d_in[1];
    const float* W1 = (const float*)d_in[2];
    const float* b1 = (const float*)d_in[3];
    const float* W2 = (const float*)d_in[4];
    const float* b2 = (const float*)d_in[5];
    float* out = (float*)d_out;

    int N = in_sizes[0] / D;
    int E = in_sizes[1] / 2;

    // 1) out = x
    {
        int n4 = N * D4;
        int threads = 256;
        int blocks = (n4 + threads - 1) / threads;
        init_kernel<<<blocks, threads>>>((const float4*)x, (float4*)out, n4);
    }

    // 2) scatter-add x[src] into out[dst]
    {
        long long total = (long long)E * D4;
        int threads = 256;
        long long want = (total + threads - 1) / threads;
        int blocks = (int)(want > 65535LL * 8LL ? 65535LL * 8LL : want);
        scatter_kernel<<<blocks, threads>>>((const float4*)x, ei, (float4*)out, E);
    }

    // 3) MLP + relu + residual (in place on out)
    {
        int threads = MLP_NT;
        int blocks = (N + threads - 1) / threads;
        size_t smem = (size_t)(2 * D * D + 2 * D + MLP_NT * D) * sizeof(float);
        cudaFuncSetAttribute(mlp_kernel, cudaFuncAttributeMaxDynamicSharedMemorySize,
                             (int)smem);
        mlp_kernel<<<blocks, threads, smem>>>(x, W1, b1, W2, b2, out, N);
    }
}

// round 3
// speedup vs baseline: 1.1804x; 1.1804x over previous
#include <cuda_runtime.h>
#include <cuda_bf16.h>
#include <cstdint>

#define D 64
#define D4 16           // D / 4
#define MLP_NT 256      // threads per block in MLP kernel

#define MAXN 102400
#define MAXE 1700000
#define SCAN_BS 1024    // elements (and threads) per scan_a block

// ------------------------- CSR scratch (device globals) ---------------------
__device__ int g_deg[MAXN];
__device__ int g_start[MAXN];
__device__ int g_cursor[MAXN];
__device__ int g_bucket[MAXE];
__device__ int g_blocksums[256];

// ---------------------------------------------------------------------------
// CSR build: zero -> histogram -> scan(a,b,c) -> fill
// ---------------------------------------------------------------------------
__global__ void zero_deg_kernel(int N) {
    int i = blockIdx.x * blockDim.x + threadIdx.x;
    if (i < N) g_deg[i] = 0;
}

__global__ void hist_kernel(const int* __restrict__ ei, int E) {
    int i = blockIdx.x * blockDim.x + threadIdx.x;
    if (i < E) atomicAdd(&g_deg[ei[E + i]], 1);
}

// block-local exclusive scan; one element per thread
__global__ void scan_a_kernel(int N) {
    __shared__ int sm[SCAN_BS];
    int gid = blockIdx.x * SCAN_BS + threadIdx.x;
    int v = (gid < N) ? g_deg[gid] : 0;
    sm[threadIdx.x] = v;
    __syncthreads();
    for (int off = 1; off < SCAN_BS; off <<= 1) {
        int t = (threadIdx.x >= off) ? sm[threadIdx.x - off] : 0;
        __syncthreads();
        sm[threadIdx.x] += t;
        __syncthreads();
    }
    if (gid < N) g_start[gid] = sm[threadIdx.x] - v;   // exclusive
    if (threadIdx.x == SCAN_BS - 1) g_blocksums[blockIdx.x] = sm[SCAN_BS - 1];
}

__global__ void scan_b_kernel(int nb) {
    __shared__ int sm[256];
    int v = (threadIdx.x < nb) ? g_blocksums[threadIdx.x] : 0;
    sm[threadIdx.x] = v;
    __syncthreads();
    for (int off = 1; off < 256; off <<= 1) {
        int t = (threadIdx.x >= off) ? sm[threadIdx.x - off] : 0;
        __syncthreads();
        sm[threadIdx.x] += t;
        __syncthreads();
    }
    if (threadIdx.x < nb) g_blocksums[threadIdx.x] = sm[threadIdx.x] - v;  // exclusive
}

__global__ void scan_c_kernel(int N) {
    int gid = blockIdx.x * blockDim.x + threadIdx.x;
    if (gid < N) {
        int s = g_start[gid] + g_blocksums[gid >> 10];   // SCAN_BS == 1024
        g_start[gid] = s;
        g_cursor[gid] = s;
    }
}

__global__ void fill_kernel(const int* __restrict__ ei, int E) {
    int i = blockIdx.x * blockDim.x + threadIdx.x;
    if (i < E) {
        int d = ei[E + i];
        int pos = atomicAdd(&g_cursor[d], 1);
        g_bucket[pos] = ei[i];   // src
    }
}

// ---------------------------------------------------------------------------
// Gather: one warp per node.  Lanes split into two halves of 16; each half
// processes one edge at a time (float4 chunk per lane -> 256B coalesced row
// read).  Halves combined by shfl, then out[node] = x[node] + agg.
// ---------------------------------------------------------------------------
__global__ void gather_kernel(const float4* __restrict__ x4,
                              float4* __restrict__ out4, int N) {
    int warp = (blockIdx.x * blockDim.x + threadIdx.x) >> 5;
    if (warp >= N) return;
    int lane = threadIdx.x & 31;
    int half = lane >> 4;
    int c = lane & 15;

    int s0 = g_start[warp];
    int dg = g_deg[warp];

    float4 acc = make_float4(0.f, 0.f, 0.f, 0.f);
    for (int j = half; j < dg; j += 2) {
        int src = g_bucket[s0 + j];
        float4 v = x4[(long long)src * D4 + c];
        acc.x += v.x; acc.y += v.y; acc.z += v.z; acc.w += v.w;
    }
    acc.x += __shfl_down_sync(0xffffffffu, acc.x, 16);
    acc.y += __shfl_down_sync(0xffffffffu, acc.y, 16);
    acc.z += __shfl_down_sync(0xffffffffu, acc.z, 16);
    acc.w += __shfl_down_sync(0xffffffffu, acc.w, 16);

    if (half == 0) {
        float4 xv = x4[(long long)warp * D4 + c];
        acc.x += xv.x; acc.y += xv.y; acc.z += xv.z; acc.w += xv.w;
        out4[(long long)warp * D4 + c] = acc;
    }
}

// ---------------------------------------------------------------------------
// Kernel 3: per-node MLP + ReLU + residual, in-place on d_out.
//   h  = d_out[node]                (= x + agg)
//   t  = relu(h @ W1 + b1)
//   o  = t @ W2 + b2
//   out[node] = x[node] + relu(o)
// ---------------------------------------------------------------------------
__global__ void mlp_kernel(const float* __restrict__ x,
                           const float* __restrict__ W1,
                           const float* __restrict__ b1,
                           const float* __restrict__ W2,
                           const float* __restrict__ b2,
                           float* __restrict__ out,
                           int N) {
    extern __shared__ float sm[];
    float* W1s = sm;                 // D*D
    float* W2s = W1s + D * D;        // D*D
    float* b1s = W2s + D * D;        // D
    float* b2s = b1s + D;            // D
    float* hs  = b2s + D;            // MLP_NT * D, layout [k][tid]

    int tid = threadIdx.x;
    for (int i = tid; i < D * D; i += MLP_NT) {
        W1s[i] = W1[i];
        W2s[i] = W2[i];
    }
    if (tid < D) { b1s[tid] = b1[tid]; b2s[tid] = b2[tid]; }
    __syncthreads();

    int node = blockIdx.x * MLP_NT + tid;
    if (node >= N) return;

    // stage h row into shared column
    {
        const float4* hrow = (const float4*)(out + (long long)node * D);
        #pragma unroll
        for (int c = 0; c < D4; c++) {
            float4 v = hrow[c];
            hs[(4 * c + 0) * MLP_NT + tid] = v.x;
            hs[(4 * c + 1) * MLP_NT + tid] = v.y;
            hs[(4 * c + 2) * MLP_NT + tid] = v.z;
            hs[(4 * c + 3) * MLP_NT + tid] = v.w;
        }
    }

    // ---- layer 1: t = relu(h @ W1 + b1), buffered in registers ----
    float t[D];
    #pragma unroll
    for (int jt = 0; jt < 4; jt++) {
        float4 acc[4];
        #pragma unroll
        for (int q = 0; q < 4; q++)
            acc[q] = ((const float4*)b1s)[jt * 4 + q];
        for (int k = 0; k < D; k++) {
            float hk = hs[k * MLP_NT + tid];
            const float4* wr = (const float4*)(W1s + k * D + jt * 16);
            #pragma unroll
            for (int q = 0; q < 4; q++) {
                float4 w = wr[q];
                acc[q].x += hk * w.x;
                acc[q].y += hk * w.y;
                acc[q].z += hk * w.z;
                acc[q].w += hk * w.w;
            }
        }
        #pragma unroll
        for (int q = 0; q < 4; q++) {
            t[jt * 16 + q * 4 + 0] = fmaxf(acc[q].x, 0.0f);
            t[jt * 16 + q * 4 + 1] = fmaxf(acc[q].y, 0.0f);
            t[jt * 16 + q * 4 + 2] = fmaxf(acc[q].z, 0.0f);
            t[jt * 16 + q * 4 + 3] = fmaxf(acc[q].w, 0.0f);
        }
    }

    // overwrite shared column with t (all reads of h are done)
    #pragma unroll
    for (int k = 0; k < D; k++) hs[k * MLP_NT + tid] = t[k];

    // ---- layer 2: o = t @ W2 + b2 ; out = x + relu(o) ----
    const float4* xrow = (const float4*)(x + (long long)node * D);
    float4* orow = (float4*)(out + (long long)node * D);
    #pragma unroll
    for (int jt = 0; jt < 4; jt++) {
        float4 acc[4];
        #pragma unroll
        for (int q = 0; q < 4; q++)
            acc[q] = ((const float4*)b2s)[jt * 4 + q];
        for (int k = 0; k < D; k++) {
            float tk = hs[k * MLP_NT + tid];
            const float4* wr = (const float4*)(W2s + k * D + jt * 16);
            #pragma unroll
            for (int q = 0; q < 4; q++) {
                float4 w = wr[q];
                acc[q].x += tk * w.x;
                acc[q].y += tk * w.y;
                acc[q].z += tk * w.z;
                acc[q].w += tk * w.w;
            }
        }
        #pragma unroll
        for (int q = 0; q < 4; q++) {
            float4 xv = xrow[jt * 4 + q];
            float4 o;
            o.x = xv.x + fmaxf(acc[q].x, 0.0f);
            o.y = xv.y + fmaxf(acc[q].y, 0.0f);
            o.z = xv.z + fmaxf(acc[q].z, 0.0f);
            o.w = xv.w + fmaxf(acc[q].w, 0.0f);
            orow[jt * 4 + q] = o;
        }
    }
}

// ---------------------------------------------------------------------------
// Launch
// inputs: 0=x [N,64] f32, 1=edge_index [2,E] i32, 2=W1 [64,64] f32,
//         3=b1 [64] f32, 4=W2 [64,64] f32, 5=b2 [64] f32
// output: [N,64] f32
// ---------------------------------------------------------------------------
extern "C" void kernel_launch(void* const* d_in, const int* in_sizes, int n_in,
                              void* d_out, int out_size) {
    const float* x  = (const float*)d_in[0];
    const int*   ei = (const int*)d_in[1];
    const float* W1 = (const float*)d_in[2];
    const float* b1 = (const float*)d_in[3];
    const float* W2 = (const float*)d_in[4];
    const float* b2 = (const float*)d_in[5];
    float* out = (float*)d_out;

    int N = in_sizes[0] / D;
    int E = in_sizes[1] / 2;

    // ---- CSR build ----
    {
        int th = 256;
        zero_deg_kernel<<<(N + th - 1) / th, th>>>(N);
        hist_kernel<<<(E + th - 1) / th, th>>>(ei, E);
        int nb = (N + SCAN_BS - 1) / SCAN_BS;
        scan_a_kernel<<<nb, SCAN_BS>>>(N);
        scan_b_kernel<<<1, 256>>>(nb);
        scan_c_kernel<<<(N + 1023) / 1024, 1024>>>(N);
        fill_kernel<<<(E + th - 1) / th, th>>>(ei, E);
    }

    // ---- gather: out = x + segment_sum(x[src] by dst) ----
    {
        int th = 256;
        long long threads = (long long)N * 32;
        int blocks = (int)((threads + th - 1) / th);
        gather_kernel<<<blocks, th>>>((const float4*)x, (float4*)out, N);
    }

    // ---- MLP + relu + residual (in place on out) ----
    {
        int threads = MLP_NT;
        int blocks = (N + threads - 1) / threads;
        size_t smem = (size_t)(2 * D * D + 2 * D + MLP_NT * D) * sizeof(float);
        cudaFuncSetAttribute(mlp_kernel, cudaFuncAttributeMaxDynamicSharedMemorySize,
                             (int)smem);
        mlp_kernel<<<blocks, threads, smem>>>(x, W1, b1, W2, b2, out, N);
    }
}